// round 5
// baseline (speedup 1.0000x reference)
#include <cuda_runtime.h>
#include <stdint.h>
#include <math.h>

#define NN 384
#define CIN 128
#define DH 32
#define NH 4
#define M_TOT (NN*NN)   // 147456

#define PAD_A 132   // fp32 smem row stride for A tiles (GEMM kernels)
#define PAD_B 136

// attention smem strides (floats) — chosen for conflict-free mma fragment access
#define SKT 392     // K^T tile [32 d][384 j]
#define SV  40      // V tile [384 j][32 d]
#define SQ  36      // Q tile [64 q][32 d]
#define SS  388     // S/P tile [64 q][384 j]
#define QT  64      // queries per q-tile

// ---------------- scratch (no allocations allowed) ----------------
__device__ float g_xn[(size_t)M_TOT*CIN];      // layernormed x (tf32-rounded), [m][c]
__device__ float g_triB[(size_t)NH*M_TOT];     // triangle bias [h][q][j]
__device__ float g_Q[(size_t)M_TOT*CIN];       // [i][h][j][d]
__device__ float g_K[(size_t)M_TOT*CIN];       // TRANSPOSED per (i,h): [i][h][d][j]
__device__ float g_V[(size_t)M_TOT*CIN];       // [i][h][j][d]
__device__ float g_G[(size_t)M_TOT*CIN];       // sigmoid gate, [i][h][j][d]
__device__ float g_OG[(size_t)M_TOT*CIN];      // gated attention out, [m][h*32+d]
__device__ float g_Bqkvg[CIN*512];             // packed weights [k][n] (tf32-rounded)
__device__ float g_Bout[CIN*CIN];              // wo transposed [k][c] (tf32-rounded)

__device__ __forceinline__ float tf32r(float x) {
    uint32_t r;
    asm("cvt.rna.tf32.f32 %0, %1;" : "=r"(r) : "f"(x));
    return __uint_as_float(r);
}

__device__ __forceinline__ void split32(float x, uint32_t& hi, uint32_t& lo) {
    float h = tf32r(x);
    hi = __float_as_uint(h);
    lo = __float_as_uint(tf32r(x - h));
}

__device__ __forceinline__ void mma8(float* c, uint32_t a0, uint32_t a1, uint32_t a2, uint32_t a3,
                                     uint32_t b0, uint32_t b1) {
    asm volatile("mma.sync.aligned.m16n8k8.row.col.f32.tf32.tf32.f32 "
        "{%0,%1,%2,%3}, {%4,%5,%6,%7}, {%8,%9}, {%0,%1,%2,%3};"
        : "+f"(c[0]), "+f"(c[1]), "+f"(c[2]), "+f"(c[3])
        : "r"(a0), "r"(a1), "r"(a2), "r"(a3), "r"(b0), "r"(b1));
}

// ---------------- K0: pack weights (tf32-rounded) ----------------
__global__ void pack_kernel(const float* __restrict__ wq, const float* __restrict__ wk,
                            const float* __restrict__ wv, const float* __restrict__ wg,
                            const float* __restrict__ wo) {
    int idx = blockIdx.x * 256 + threadIdx.x;
    if (idx < CIN * 512) {
        int k = idx >> 9, n = idx & 511;
        int h = n >> 7, t = n & 127, sub = t >> 5, d = t & 31;
        const float* w = (sub == 0) ? wq : (sub == 1) ? wk : (sub == 2) ? wv : wg;
        float val = w[(h * DH + d) * CIN + k];
        if (sub == 0) val *= 0.17677669529663687f;   // 1/sqrt(32)
        g_Bqkvg[idx] = tf32r(val);
    }
    if (idx < CIN * CIN) {
        int k = idx >> 7, c = idx & 127;
        g_Bout[idx] = tf32r(wo[c * CIN + k]);
    }
}

// ---------------- K1: LayerNorm + triangle bias ----------------
__global__ void __launch_bounds__(256) ln_kernel(const float* __restrict__ x,
                                                 const float* __restrict__ gamma,
                                                 const float* __restrict__ beta,
                                                 const float* __restrict__ wbias) {
    int wid = threadIdx.x >> 5, lane = threadIdx.x & 31;
    int p = blockIdx.x * 8 + wid;
    const float4 v = ((const float4*)(x + (size_t)p * CIN))[lane];
    float s  = v.x + v.y + v.z + v.w;
    float sq = v.x*v.x + v.y*v.y + v.z*v.z + v.w*v.w;
    #pragma unroll
    for (int o = 16; o; o >>= 1) {
        s  += __shfl_xor_sync(~0u, s,  o);
        sq += __shfl_xor_sync(~0u, sq, o);
    }
    float mu   = s * (1.f / 128.f);
    float var  = sq * (1.f / 128.f) - mu * mu;
    float rstd = rsqrtf(var + 1e-5f);
    float4 g4 = ((const float4*)gamma)[lane];
    float4 b4 = ((const float4*)beta)[lane];
    float4 xn;
    xn.x = (v.x - mu) * rstd * g4.x + b4.x;
    xn.y = (v.y - mu) * rstd * g4.y + b4.y;
    xn.z = (v.z - mu) * rstd * g4.z + b4.z;
    xn.w = (v.w - mu) * rstd * g4.w + b4.w;

    #pragma unroll
    for (int h = 0; h < NH; h++) {
        float4 w4 = ((const float4*)(wbias + h * CIN))[lane];
        float d = xn.x*w4.x + xn.y*w4.y + xn.z*w4.z + xn.w*w4.w;
        #pragma unroll
        for (int o = 16; o; o >>= 1) d += __shfl_xor_sync(~0u, d, o);
        if (lane == 0) g_triB[(size_t)h * M_TOT + p] = d;  // [h][q=i][j]
    }

    float4 xr;
    xr.x = tf32r(xn.x); xr.y = tf32r(xn.y); xr.z = tf32r(xn.z); xr.w = tf32r(xn.w);
    ((float4*)(g_xn + (size_t)p * CIN))[lane] = xr;
}

// ---------------- K2: projection GEMM via mma.sync tf32 ----------------
__global__ void __launch_bounds__(256, 1) proj_mma_kernel(const float* __restrict__ bg) {
    extern __shared__ float sm[];
    float* As = sm;                    // [128][PAD_A]
    float* Bs = sm + 128 * PAD_A;      // [128][PAD_B]
    int tid = threadIdx.x;
    int h   = blockIdx.x;
    int m0  = blockIdx.y * 128;

    const float4* Ag = (const float4*)(g_xn + (size_t)m0 * CIN);
    const float4* Bg = (const float4*)g_Bqkvg;
    #pragma unroll
    for (int r = 0; r < 16; r++) {
        int f = tid + r * 256;
        int row = f >> 5, c4 = f & 31;
        *(float4*)(As + row * PAD_A + c4 * 4) = Ag[f];
        *(float4*)(Bs + row * PAD_B + c4 * 4) = Bg[row * 128 + h * 32 + c4];
    }
    __syncthreads();

    int warp = tid >> 5, lane = tid & 31;
    int wm = (warp >> 1) * 32;
    int wn = (warp & 1) * 64;
    int g  = lane >> 2, tg = lane & 3;

    float c[2][8][4];
    #pragma unroll
    for (int a = 0; a < 2; a++)
        #pragma unroll
        for (int b = 0; b < 8; b++)
            #pragma unroll
            for (int e = 0; e < 4; e++) c[a][b][e] = 0.f;

    for (int k0 = 0; k0 < 128; k0 += 8) {
        uint32_t a[2][4];
        #pragma unroll
        for (int mt = 0; mt < 2; mt++) {
            const float* ap = As + (wm + mt * 16 + g) * PAD_A + k0 + tg;
            a[mt][0] = __float_as_uint(ap[0]);
            a[mt][1] = __float_as_uint(ap[8 * PAD_A]);
            a[mt][2] = __float_as_uint(ap[4]);
            a[mt][3] = __float_as_uint(ap[8 * PAD_A + 4]);
        }
        #pragma unroll
        for (int nt = 0; nt < 8; nt++) {
            const float* bp = Bs + (k0 + tg) * PAD_B + wn + nt * 8 + g;
            uint32_t b0 = __float_as_uint(bp[0]);
            uint32_t b1 = __float_as_uint(bp[4 * PAD_B]);
            #pragma unroll
            for (int mt = 0; mt < 2; mt++)
                mma8(c[mt][nt], a[mt][0], a[mt][1], a[mt][2], a[mt][3], b0, b1);
        }
    }

    // epilogue: scatter into Q/K^T/V/G
    #pragma unroll
    for (int nt = 0; nt < 8; nt++) {
        int n = wn + nt * 8 + 2 * tg;
        int sub = n >> 5, d0 = n & 31;
        float bg0 = 0.f, bg1 = 0.f;
        if (sub == 3) { bg0 = bg[h * DH + d0]; bg1 = bg[h * DH + d0 + 1]; }
        #pragma unroll
        for (int mt = 0; mt < 2; mt++) {
            #pragma unroll
            for (int rr = 0; rr < 2; rr++) {
                int m = m0 + wm + mt * 16 + g + rr * 8;
                int i = m / NN, j = m - i * NN;
                float v0 = c[mt][nt][rr * 2 + 0];
                float v1 = c[mt][nt][rr * 2 + 1];
                size_t hb = (size_t)(i * NH + h) * NN * DH;
                if (sub == 1) {
                    // K stored transposed: [d][j]
                    g_K[hb + (size_t)d0 * NN + j]       = v0;
                    g_K[hb + (size_t)(d0 + 1) * NN + j] = v1;
                } else if (sub == 3) {
                    v0 = 1.f / (1.f + __expf(-(v0 + bg0)));
                    v1 = 1.f / (1.f + __expf(-(v1 + bg1)));
                    *(float2*)(g_G + hb + (size_t)j * DH + d0) = make_float2(v0, v1);
                } else {
                    float* dst = ((sub == 0) ? g_Q : g_V) + hb + (size_t)j * DH + d0;
                    *(float2*)dst = make_float2(v0, v1);
                }
            }
        }
    }
}

// ---------------- K3: attention via tensor cores (3xTF32) ----------------
__global__ void __launch_bounds__(256, 1) attn_mma_kernel(const float* __restrict__ mask) {
    extern __shared__ float sm[];
    float* Ks = sm;                       // [32][SKT]   K^T
    float* Vs = Ks + 32 * SKT;            // [384][SV]
    float* Qs = Vs + NN * SV;             // [64][SQ]
    float* Ss = Qs + QT * SQ;             // [64][SS]
    float* Lr = Ss + QT * SS;             // [64] inverse row sums

    int i = blockIdx.x, h = blockIdx.y;
    int tid = threadIdx.x, warp = tid >> 5, lane = tid & 31;
    int g = lane >> 2, tg = lane & 3;
    size_t base = (size_t)(i * NH + h) * NN * DH;

    // load K^T and V into smem (coalesced gmem, conflict-free STS.128)
    const float4* KTg = (const float4*)(g_K + base);
    const float4* Vg  = (const float4*)(g_V + base);
    #pragma unroll
    for (int r = 0; r < 12; r++) {
        int f = tid + r * 256;          // 3072 float4s
        int d = f / 96, j4 = f - d * 96;
        *(float4*)(Ks + d * SKT + j4 * 4) = KTg[f];
        int j = f >> 3, d4 = f & 7;
        *(float4*)(Vs + j * SV + d4 * 4) = Vg[f];
    }
    float mb[12];
    #pragma unroll
    for (int t = 0; t < 12; t++)
        mb[t] = (__ldg(mask + (size_t)i * NN + lane + t * 32) - 1.f) * 1e9f;
    __syncthreads();

    for (int qt = 0; qt < NN / QT; qt++) {
        // ---- load Q tile ----
        const float4* Qg = (const float4*)(g_Q + base + (size_t)qt * QT * DH);
        #pragma unroll
        for (int r = 0; r < 2; r++) {
            int f = tid + r * 256;      // 512 float4s
            int q = f >> 3, d4 = f & 7;
            *(float4*)(Qs + q * SQ + d4 * 4) = Qg[f];
        }
        __syncthreads();

        // ---- S = Q @ K^T (3xTF32) ----
        {
            int wm = (warp >> 2) * 32;        // 2 warps in M
            int n0 = (warp & 3) * 96;         // 4 warps in N
            float c[2][12][4];
            #pragma unroll
            for (int a = 0; a < 2; a++)
                #pragma unroll
                for (int b = 0; b < 12; b++)
                    #pragma unroll
                    for (int e = 0; e < 4; e++) c[a][b][e] = 0.f;

            #pragma unroll
            for (int k0 = 0; k0 < 32; k0 += 8) {
                uint32_t ahi[2][4], alo[2][4];
                #pragma unroll
                for (int mt = 0; mt < 2; mt++) {
                    const float* ap = Qs + (wm + mt * 16 + g) * SQ + k0 + tg;
                    split32(ap[0],          ahi[mt][0], alo[mt][0]);
                    split32(ap[8 * SQ],     ahi[mt][1], alo[mt][1]);
                    split32(ap[4],          ahi[mt][2], alo[mt][2]);
                    split32(ap[8 * SQ + 4], ahi[mt][3], alo[mt][3]);
                }
                #pragma unroll
                for (int nt = 0; nt < 12; nt++) {
                    const float* bp = Ks + (k0 + tg) * SKT + n0 + nt * 8 + g;
                    uint32_t bh0, bl0, bh1, bl1;
                    split32(bp[0],       bh0, bl0);
                    split32(bp[4 * SKT], bh1, bl1);
                    #pragma unroll
                    for (int mt = 0; mt < 2; mt++) {
                        mma8(c[mt][nt], ahi[mt][0], ahi[mt][1], ahi[mt][2], ahi[mt][3], bh0, bh1);
                        mma8(c[mt][nt], ahi[mt][0], ahi[mt][1], ahi[mt][2], ahi[mt][3], bl0, bl1);
                        mma8(c[mt][nt], alo[mt][0], alo[mt][1], alo[mt][2], alo[mt][3], bh0, bh1);
                    }
                }
            }
            // store S
            #pragma unroll
            for (int mt = 0; mt < 2; mt++) {
                #pragma unroll
                for (int nt = 0; nt < 12; nt++) {
                    int row = wm + mt * 16 + g;
                    int col = n0 + nt * 8 + 2 * tg;
                    *(float2*)(Ss + row * SS + col)       = make_float2(c[mt][nt][0], c[mt][nt][1]);
                    *(float2*)(Ss + (row + 8) * SS + col) = make_float2(c[mt][nt][2], c[mt][nt][3]);
                }
            }
        }
        __syncthreads();

        // ---- softmax (bias + mask), each warp 8 rows ----
        {
            int qg0 = qt * QT;
            for (int rr = 0; rr < 8; rr++) {
                int row = warp * 8 + rr;
                const float* bias = g_triB + (size_t)h * M_TOT + (size_t)(qg0 + row) * NN;
                float vv[12], mx = -1e30f;
                #pragma unroll
                for (int t = 0; t < 12; t++) {
                    float v = Ss[row * SS + lane + t * 32] + __ldg(bias + lane + t * 32) + mb[t];
                    vv[t] = v; mx = fmaxf(mx, v);
                }
                #pragma unroll
                for (int o = 16; o; o >>= 1) mx = fmaxf(mx, __shfl_xor_sync(~0u, mx, o));
                float s = 0.f;
                #pragma unroll
                for (int t = 0; t < 12; t++) {
                    float p = __expf(vv[t] - mx);
                    s += p;
                    Ss[row * SS + lane + t * 32] = p;
                }
                #pragma unroll
                for (int o = 16; o; o >>= 1) s += __shfl_xor_sync(~0u, s, o);
                if (lane == 0) Lr[row] = 1.f / s;
            }
        }
        __syncthreads();

        // ---- O = P @ V (3xTF32) + gate + store ----
        {
            int wm2 = (warp & 3) * 16;    // 4 warps in M
            int wn2 = (warp >> 2) * 16;   // 2 warps in N
            float c2[2][4];
            #pragma unroll
            for (int b = 0; b < 2; b++)
                #pragma unroll
                for (int e = 0; e < 4; e++) c2[b][e] = 0.f;

            for (int k0 = 0; k0 < NN; k0 += 8) {
                const float* ap = Ss + (wm2 + g) * SS + k0 + tg;
                uint32_t ahi[4], alo[4];
                split32(ap[0],          ahi[0], alo[0]);
                split32(ap[8 * SS],     ahi[1], alo[1]);
                split32(ap[4],          ahi[2], alo[2]);
                split32(ap[8 * SS + 4], ahi[3], alo[3]);
                #pragma unroll
                for (int nt = 0; nt < 2; nt++) {
                    const float* bp = Vs + (k0 + tg) * SV + wn2 + nt * 8 + g;
                    uint32_t bh0, bl0, bh1, bl1;
                    split32(bp[0],      bh0, bl0);
                    split32(bp[4 * SV], bh1, bl1);
                    mma8(c2[nt], ahi[0], ahi[1], ahi[2], ahi[3], bh0, bh1);
                    mma8(c2[nt], ahi[0], ahi[1], ahi[2], ahi[3], bl0, bl1);
                    mma8(c2[nt], alo[0], alo[1], alo[2], alo[3], bh0, bh1);
                }
            }
            #pragma unroll
            for (int nt = 0; nt < 2; nt++) {
                int col = wn2 + nt * 8 + 2 * tg;       // d
                #pragma unroll
                for (int e2 = 0; e2 < 2; e2++) {
                    int row = wm2 + g + e2 * 8;
                    int q = qt * QT + row;
                    float li = Lr[row];
                    float2 gg = *(const float2*)(g_G + base + (size_t)q * DH + col);
                    float o0 = c2[nt][e2 * 2 + 0] * li * gg.x;
                    float o1 = c2[nt][e2 * 2 + 1] * li * gg.y;
                    *(float2*)(g_OG + (size_t)(i * NN + q) * CIN + h * DH + col) = make_float2(o0, o1);
                }
            }
        }
        __syncthreads();
    }
}

// ---------------- K4: output GEMM via mma.sync tf32 ----------------
__global__ void __launch_bounds__(256, 1) out_mma_kernel(const float* __restrict__ bo,
                                                         float* __restrict__ out) {
    extern __shared__ float sm[];
    float* As = sm;
    float* Bs = sm + 128 * PAD_A;
    int tid = threadIdx.x;
    int m0  = blockIdx.x * 128;

    const float4* Ag = (const float4*)(g_OG + (size_t)m0 * CIN);
    const float4* Bg = (const float4*)g_Bout;
    #pragma unroll
    for (int r = 0; r < 16; r++) {
        int f = tid + r * 256;
        int row = f >> 5, c4 = f & 31;
        float4 av = Ag[f];
        av.x = tf32r(av.x); av.y = tf32r(av.y); av.z = tf32r(av.z); av.w = tf32r(av.w);
        *(float4*)(As + row * PAD_A + c4 * 4) = av;
        *(float4*)(Bs + row * PAD_B + c4 * 4) = Bg[f];
    }
    __syncthreads();

    int warp = tid >> 5, lane = tid & 31;
    int wm = (warp >> 1) * 32;
    int wn = (warp & 1) * 64;
    int g  = lane >> 2, tg = lane & 3;

    float c[2][8][4];
    #pragma unroll
    for (int a = 0; a < 2; a++)
        #pragma unroll
        for (int b = 0; b < 8; b++)
            #pragma unroll
            for (int e = 0; e < 4; e++) c[a][b][e] = 0.f;

    for (int k0 = 0; k0 < 128; k0 += 8) {
        uint32_t a[2][4];
        #pragma unroll
        for (int mt = 0; mt < 2; mt++) {
            const float* ap = As + (wm + mt * 16 + g) * PAD_A + k0 + tg;
            a[mt][0] = __float_as_uint(ap[0]);
            a[mt][1] = __float_as_uint(ap[8 * PAD_A]);
            a[mt][2] = __float_as_uint(ap[4]);
            a[mt][3] = __float_as_uint(ap[8 * PAD_A + 4]);
        }
        #pragma unroll
        for (int nt = 0; nt < 8; nt++) {
            const float* bp = Bs + (k0 + tg) * PAD_B + wn + nt * 8 + g;
            uint32_t b0 = __float_as_uint(bp[0]);
            uint32_t b1 = __float_as_uint(bp[4 * PAD_B]);
            #pragma unroll
            for (int mt = 0; mt < 2; mt++)
                mma8(c[mt][nt], a[mt][0], a[mt][1], a[mt][2], a[mt][3], b0, b1);
        }
    }

    #pragma unroll
    for (int nt = 0; nt < 8; nt++) {
        int n = wn + nt * 8 + 2 * tg;
        float bo0 = bo[n], bo1 = bo[n + 1];
        #pragma unroll
        for (int mt = 0; mt < 2; mt++) {
            #pragma unroll
            for (int rr = 0; rr < 2; rr++) {
                int m = m0 + wm + mt * 16 + g + rr * 8;
                float* dst = out + (size_t)m * CIN + n;
                *(float2*)dst = make_float2(c[mt][nt][rr*2+0] + bo0,
                                            c[mt][nt][rr*2+1] + bo1);
            }
        }
    }
}

// ---------------- launch ----------------
extern "C" void kernel_launch(void* const* d_in, const int* in_sizes, int n_in,
                              void* d_out, int out_size) {
    const float* x     = (const float*)d_in[0];
    const float* mask  = (const float*)d_in[1];
    const float* gamma = (const float*)d_in[2];
    const float* beta  = (const float*)d_in[3];
    const float* wbias = (const float*)d_in[4];
    const float* wq    = (const float*)d_in[5];
    const float* wk    = (const float*)d_in[6];
    const float* wv    = (const float*)d_in[7];
    const float* wg    = (const float*)d_in[8];
    const float* bg    = (const float*)d_in[9];
    const float* wo    = (const float*)d_in[10];
    const float* bo    = (const float*)d_in[11];
    float* out = (float*)d_out;

    const int smem_gemm = 128 * PAD_A * 4 + 128 * PAD_B * 4;              // 137216
    const int smem_attn = (32*SKT + NN*SV + QT*SQ + QT*SS + QT) * 4;      // 220416
    cudaFuncSetAttribute(proj_mma_kernel, cudaFuncAttributeMaxDynamicSharedMemorySize, smem_gemm);
    cudaFuncSetAttribute(out_mma_kernel,  cudaFuncAttributeMaxDynamicSharedMemorySize, smem_gemm);
    cudaFuncSetAttribute(attn_mma_kernel, cudaFuncAttributeMaxDynamicSharedMemorySize, smem_attn);

    pack_kernel<<<256, 256>>>(wq, wk, wv, wg, wo);
    ln_kernel<<<M_TOT / 8, 256>>>(x, gamma, beta, wbias);
    proj_mma_kernel<<<dim3(NH, M_TOT / 128), 256, smem_gemm>>>(bg);
    attn_mma_kernel<<<dim3(NN, NH), 256, smem_attn>>>(mask);
    out_mma_kernel<<<M_TOT / 128, 256, smem_gemm>>>(bo, out);
}

// round 8
// speedup vs baseline: 1.8364x; 1.8364x over previous
#include <cuda_runtime.h>
#include <cuda_bf16.h>
#include <stdint.h>
#include <math.h>

#define NN 384
#define CIN 128
#define DH 32
#define NH 4
#define M_TOT (NN*NN)   // 147456

#define PAD_A 132
#define PAD_B 136

// ---------------- scratch ----------------
__device__ float g_xn[(size_t)M_TOT*CIN];       // layernormed x (tf32-rounded)
__device__ float g_triB[(size_t)NH*M_TOT];      // triangle bias [h][q][j]
__device__ float g_G[(size_t)M_TOT*CIN];        // sigmoid gate [i][h][j][d] fp32
__device__ float g_OG[(size_t)M_TOT*CIN];       // gated attention out [m][h*32+d]
__device__ float g_Bqkvg[CIN*512];
__device__ float g_Bout[CIN*CIN];
// bf16 hi/lo planes for attention operands — sized for ALL heads: M_TOT*NH*DH = M_TOT*CIN
__device__ __nv_bfloat16 g_Qh[(size_t)M_TOT*CIN];   // [i][h][j][d]
__device__ __nv_bfloat16 g_Ql[(size_t)M_TOT*CIN];
__device__ __nv_bfloat16 g_Kh[(size_t)M_TOT*CIN];   // [i][h][j][d]
__device__ __nv_bfloat16 g_Kl[(size_t)M_TOT*CIN];
__device__ __nv_bfloat16 g_Vth[(size_t)M_TOT*CIN];  // TRANSPOSED [i][h][d][j]
__device__ __nv_bfloat16 g_Vtl[(size_t)M_TOT*CIN];

__device__ __forceinline__ float tf32r(float x) {
    uint32_t r;
    asm("cvt.rna.tf32.f32 %0, %1;" : "=r"(r) : "f"(x));
    return __uint_as_float(r);
}

__device__ __forceinline__ void split_pk(float a, float b, uint32_t& hi, uint32_t& lo) {
    __nv_bfloat162 H, L;
    H.x = __float2bfloat16_rn(a); H.y = __float2bfloat16_rn(b);
    L.x = __float2bfloat16_rn(a - __bfloat162float(H.x));
    L.y = __float2bfloat16_rn(b - __bfloat162float(H.y));
    hi = *(uint32_t*)&H; lo = *(uint32_t*)&L;
}

__device__ __forceinline__ void mma_tf32(float* c, uint32_t a0, uint32_t a1, uint32_t a2, uint32_t a3,
                                         uint32_t b0, uint32_t b1) {
    asm volatile("mma.sync.aligned.m16n8k8.row.col.f32.tf32.tf32.f32 "
        "{%0,%1,%2,%3}, {%4,%5,%6,%7}, {%8,%9}, {%0,%1,%2,%3};"
        : "+f"(c[0]), "+f"(c[1]), "+f"(c[2]), "+f"(c[3])
        : "r"(a0), "r"(a1), "r"(a2), "r"(a3), "r"(b0), "r"(b1));
}

__device__ __forceinline__ void mma_bf16(float* c, const uint32_t* a, uint32_t b0, uint32_t b1) {
    asm volatile("mma.sync.aligned.m16n8k16.row.col.f32.bf16.bf16.f32 "
        "{%0,%1,%2,%3}, {%4,%5,%6,%7}, {%8,%9}, {%0,%1,%2,%3};"
        : "+f"(c[0]), "+f"(c[1]), "+f"(c[2]), "+f"(c[3])
        : "r"(a[0]), "r"(a[1]), "r"(a[2]), "r"(a[3]), "r"(b0), "r"(b1));
}

// ---------------- K0: pack weights ----------------
__global__ void pack_kernel(const float* __restrict__ wq, const float* __restrict__ wk,
                            const float* __restrict__ wv, const float* __restrict__ wg,
                            const float* __restrict__ wo) {
    int idx = blockIdx.x * 256 + threadIdx.x;
    if (idx < CIN * 512) {
        int k = idx >> 9, n = idx & 511;
        int h = n >> 7, t = n & 127, sub = t >> 5, d = t & 31;
        const float* w = (sub == 0) ? wq : (sub == 1) ? wk : (sub == 2) ? wv : wg;
        float val = w[(h * DH + d) * CIN + k];
        if (sub == 0) val *= 0.17677669529663687f;
        g_Bqkvg[idx] = tf32r(val);
    }
    if (idx < CIN * CIN) {
        int k = idx >> 7, c = idx & 127;
        g_Bout[idx] = tf32r(wo[c * CIN + k]);
    }
}

// ---------------- K1: LayerNorm + triangle bias ----------------
__global__ void __launch_bounds__(256) ln_kernel(const float* __restrict__ x,
                                                 const float* __restrict__ gamma,
                                                 const float* __restrict__ beta,
                                                 const float* __restrict__ wbias) {
    int wid = threadIdx.x >> 5, lane = threadIdx.x & 31;
    int p = blockIdx.x * 8 + wid;
    const float4 v = ((const float4*)(x + (size_t)p * CIN))[lane];
    float s  = v.x + v.y + v.z + v.w;
    float sq = v.x*v.x + v.y*v.y + v.z*v.z + v.w*v.w;
    #pragma unroll
    for (int o = 16; o; o >>= 1) {
        s  += __shfl_xor_sync(~0u, s,  o);
        sq += __shfl_xor_sync(~0u, sq, o);
    }
    float mu   = s * (1.f / 128.f);
    float var  = sq * (1.f / 128.f) - mu * mu;
    float rstd = rsqrtf(var + 1e-5f);
    float4 g4 = ((const float4*)gamma)[lane];
    float4 b4 = ((const float4*)beta)[lane];
    float4 xn;
    xn.x = (v.x - mu) * rstd * g4.x + b4.x;
    xn.y = (v.y - mu) * rstd * g4.y + b4.y;
    xn.z = (v.z - mu) * rstd * g4.z + b4.z;
    xn.w = (v.w - mu) * rstd * g4.w + b4.w;

    #pragma unroll
    for (int h = 0; h < NH; h++) {
        float4 w4 = ((const float4*)(wbias + h * CIN))[lane];
        float d = xn.x*w4.x + xn.y*w4.y + xn.z*w4.z + xn.w*w4.w;
        #pragma unroll
        for (int o = 16; o; o >>= 1) d += __shfl_xor_sync(~0u, d, o);
        if (lane == 0) g_triB[(size_t)h * M_TOT + p] = d;
    }

    float4 xr;
    xr.x = tf32r(xn.x); xr.y = tf32r(xn.y); xr.z = tf32r(xn.z); xr.w = tf32r(xn.w);
    ((float4*)(g_xn + (size_t)p * CIN))[lane] = xr;
}

// ---------------- K2: projection GEMM (tf32 mma) + bf16 split epilogue ----------------
__global__ void __launch_bounds__(256, 1) proj_mma_kernel(const float* __restrict__ bg) {
    extern __shared__ float sm[];
    float* As = sm;
    float* Bs = sm + 128 * PAD_A;
    int tid = threadIdx.x;
    int h   = blockIdx.x;
    int m0  = blockIdx.y * 128;

    const float4* Ag = (const float4*)(g_xn + (size_t)m0 * CIN);
    const float4* Bg = (const float4*)g_Bqkvg;
    #pragma unroll
    for (int r = 0; r < 16; r++) {
        int f = tid + r * 256;
        int row = f >> 5, c4 = f & 31;
        *(float4*)(As + row * PAD_A + c4 * 4) = Ag[f];
        *(float4*)(Bs + row * PAD_B + c4 * 4) = Bg[row * 128 + h * 32 + c4];
    }
    __syncthreads();

    int warp = tid >> 5, lane = tid & 31;
    int wm = (warp >> 1) * 32;
    int wn = (warp & 1) * 64;
    int g  = lane >> 2, tg = lane & 3;

    float c[2][8][4];
    #pragma unroll
    for (int a = 0; a < 2; a++)
        #pragma unroll
        for (int b = 0; b < 8; b++)
            #pragma unroll
            for (int e = 0; e < 4; e++) c[a][b][e] = 0.f;

    for (int k0 = 0; k0 < 128; k0 += 8) {
        uint32_t a[2][4];
        #pragma unroll
        for (int mt = 0; mt < 2; mt++) {
            const float* ap = As + (wm + mt * 16 + g) * PAD_A + k0 + tg;
            a[mt][0] = __float_as_uint(ap[0]);
            a[mt][1] = __float_as_uint(ap[8 * PAD_A]);
            a[mt][2] = __float_as_uint(ap[4]);
            a[mt][3] = __float_as_uint(ap[8 * PAD_A + 4]);
        }
        #pragma unroll
        for (int nt = 0; nt < 8; nt++) {
            const float* bp = Bs + (k0 + tg) * PAD_B + wn + nt * 8 + g;
            uint32_t b0 = __float_as_uint(bp[0]);
            uint32_t b1 = __float_as_uint(bp[4 * PAD_B]);
            #pragma unroll
            for (int mt = 0; mt < 2; mt++)
                mma_tf32(c[mt][nt], a[mt][0], a[mt][1], a[mt][2], a[mt][3], b0, b1);
        }
    }

    #pragma unroll
    for (int nt = 0; nt < 8; nt++) {
        int n = wn + nt * 8 + 2 * tg;
        int sub = n >> 5, d0 = n & 31;
        float bg0 = 0.f, bg1 = 0.f;
        if (sub == 3) { bg0 = bg[h * DH + d0]; bg1 = bg[h * DH + d0 + 1]; }
        #pragma unroll
        for (int mt = 0; mt < 2; mt++) {
            #pragma unroll
            for (int rr = 0; rr < 2; rr++) {
                int m = m0 + wm + mt * 16 + g + rr * 8;
                int i = m / NN, j = m - i * NN;
                float v0 = c[mt][nt][rr * 2 + 0];
                float v1 = c[mt][nt][rr * 2 + 1];
                size_t hb = (size_t)(i * NH + h) * NN * DH;
                if (sub == 3) {
                    v0 = 1.f / (1.f + __expf(-(v0 + bg0)));
                    v1 = 1.f / (1.f + __expf(-(v1 + bg1)));
                    *(float2*)(g_G + hb + (size_t)j * DH + d0) = make_float2(v0, v1);
                } else if (sub == 2) {
                    // V transposed bf16 hi/lo planes
                    __nv_bfloat16 h0 = __float2bfloat16_rn(v0);
                    __nv_bfloat16 h1 = __float2bfloat16_rn(v1);
                    g_Vth[hb + (size_t)d0 * NN + j]       = h0;
                    g_Vth[hb + (size_t)(d0 + 1) * NN + j] = h1;
                    g_Vtl[hb + (size_t)d0 * NN + j]       = __float2bfloat16_rn(v0 - __bfloat162float(h0));
                    g_Vtl[hb + (size_t)(d0 + 1) * NN + j] = __float2bfloat16_rn(v1 - __bfloat162float(h1));
                } else {
                    uint32_t hi, lo;
                    split_pk(v0, v1, hi, lo);
                    __nv_bfloat16* dh = ((sub == 0) ? g_Qh : g_Kh) + hb + (size_t)j * DH + d0;
                    __nv_bfloat16* dl = ((sub == 0) ? g_Ql : g_Kl) + hb + (size_t)j * DH + d0;
                    *(uint32_t*)dh = hi;
                    *(uint32_t*)dl = lo;
                }
            }
        }
    }
}

// ---------------- K3: attention, bf16 3-term mma, flash-style ----------------
// smem u32 layout: Ksh[384*20], Ksl[384*20], Vth[32*196], Vtl[32*196], ms[384]f
__global__ void __launch_bounds__(256) attn_bf16_kernel(const float* __restrict__ mask) {
    extern __shared__ uint32_t smu[];
    uint32_t* Ksh = smu;             // [j=384][20]  (32 d = 16 u32, pad 4)
    uint32_t* Ksl = smu + 7680;
    uint32_t* Vts = smu + 15360;     // hi [d=32][196] (384 j = 192 u32, pad 4)
    uint32_t* Vtl = smu + 21632;
    float*    ms  = (float*)(smu + 27904);   // [384]

    int i = blockIdx.x, h = blockIdx.y;
    int tid = threadIdx.x, warp = tid >> 5, lane = tid & 31;
    int g = lane >> 2, tg = lane & 3;
    size_t base = (size_t)(i * NH + h) * NN * DH;

    {
        const uint2* Kh2 = (const uint2*)(g_Kh + base);
        const uint2* Kl2 = (const uint2*)(g_Kl + base);
        const uint2* Vh2 = (const uint2*)(g_Vth + base);
        const uint2* Vl2 = (const uint2*)(g_Vtl + base);
        #pragma unroll
        for (int r = 0; r < 12; r++) {
            int f = tid + r * 256;           // 3072 uint2
            int j = f >> 3, d4 = f & 7;
            *(uint2*)(Ksh + j * 20 + 2 * d4) = Kh2[f];
            *(uint2*)(Ksl + j * 20 + 2 * d4) = Kl2[f];
            int d = f / 96, j4 = f - d * 96;
            *(uint2*)(Vts + d * 196 + 2 * j4) = Vh2[f];
            *(uint2*)(Vtl + d * 196 + 2 * j4) = Vl2[f];
        }
        for (int t = tid; t < NN; t += 256)
            ms[t] = (__ldg(mask + (size_t)i * NN + t) - 1.f) * 1e9f;
    }
    __syncthreads();

    const float* biasH = g_triB + (size_t)h * M_TOT;
    const uint32_t* Qhp = (const uint32_t*)(g_Qh + base);
    const uint32_t* Qlp = (const uint32_t*)(g_Ql + base);

    for (int qt = 0; qt < 3; qt++) {
        int q0 = qt * 128 + warp * 16;

        uint32_t aQh[2][4], aQl[2][4];
        #pragma unroll
        for (int kc = 0; kc < 2; kc++) {
            int u0 = (q0 + g) * 16 + kc * 8 + tg;
            int u1 = (q0 + g + 8) * 16 + kc * 8 + tg;
            aQh[kc][0] = __ldg(Qhp + u0);     aQh[kc][1] = __ldg(Qhp + u1);
            aQh[kc][2] = __ldg(Qhp + u0 + 4); aQh[kc][3] = __ldg(Qhp + u1 + 4);
            aQl[kc][0] = __ldg(Qlp + u0);     aQl[kc][1] = __ldg(Qlp + u1);
            aQl[kc][2] = __ldg(Qlp + u0 + 4); aQl[kc][3] = __ldg(Qlp + u1 + 4);
        }

        float m0 = -1e30f, m1 = -1e30f, l0 = 0.f, l1 = 0.f;
        float O[4][4];
        #pragma unroll
        for (int a = 0; a < 4; a++)
            #pragma unroll
            for (int e = 0; e < 4; e++) O[a][e] = 0.f;

        for (int ch = 0; ch < 6; ch++) {
            int j0 = ch * 64;
            float c[8][4];
            #pragma unroll
            for (int nt = 0; nt < 8; nt++)
                #pragma unroll
                for (int e = 0; e < 4; e++) c[nt][e] = 0.f;

            // S = Q K^T, 3-term bf16
            #pragma unroll
            for (int nt = 0; nt < 8; nt++) {
                int jb = (j0 + nt * 8 + g) * 20 + tg;
                #pragma unroll
                for (int kc = 0; kc < 2; kc++) {
                    uint32_t bh0 = Ksh[jb + kc * 8],     bh1 = Ksh[jb + kc * 8 + 4];
                    uint32_t bl0 = Ksl[jb + kc * 8],     bl1 = Ksl[jb + kc * 8 + 4];
                    mma_bf16(c[nt], aQh[kc], bh0, bh1);
                    mma_bf16(c[nt], aQh[kc], bl0, bl1);
                    mma_bf16(c[nt], aQl[kc], bh0, bh1);
                }
            }

            // bias + mask, row max
            float mx0 = -1e30f, mx1 = -1e30f;
            #pragma unroll
            for (int nt = 0; nt < 8; nt++) {
                int jj = j0 + nt * 8 + 2 * tg;
                float2 b0 = __ldg((const float2*)(biasH + (size_t)(q0 + g) * NN + jj));
                float2 b1 = __ldg((const float2*)(biasH + (size_t)(q0 + g + 8) * NN + jj));
                float2 mm = *(float2*)(ms + jj);
                c[nt][0] += b0.x + mm.x; c[nt][1] += b0.y + mm.y;
                c[nt][2] += b1.x + mm.x; c[nt][3] += b1.y + mm.y;
                mx0 = fmaxf(mx0, fmaxf(c[nt][0], c[nt][1]));
                mx1 = fmaxf(mx1, fmaxf(c[nt][2], c[nt][3]));
            }
            mx0 = fmaxf(mx0, __shfl_xor_sync(~0u, mx0, 1));
            mx0 = fmaxf(mx0, __shfl_xor_sync(~0u, mx0, 2));
            mx1 = fmaxf(mx1, __shfl_xor_sync(~0u, mx1, 1));
            mx1 = fmaxf(mx1, __shfl_xor_sync(~0u, mx1, 2));

            float mn0 = fmaxf(m0, mx0), mn1 = fmaxf(m1, mx1);
            float cr0 = __expf(m0 - mn0), cr1 = __expf(m1 - mn1);
            float s0 = 0.f, s1 = 0.f;
            #pragma unroll
            for (int nt = 0; nt < 8; nt++) {
                c[nt][0] = __expf(c[nt][0] - mn0); c[nt][1] = __expf(c[nt][1] - mn0);
                c[nt][2] = __expf(c[nt][2] - mn1); c[nt][3] = __expf(c[nt][3] - mn1);
                s0 += c[nt][0] + c[nt][1];
                s1 += c[nt][2] + c[nt][3];
            }
            s0 += __shfl_xor_sync(~0u, s0, 1); s0 += __shfl_xor_sync(~0u, s0, 2);
            s1 += __shfl_xor_sync(~0u, s1, 1); s1 += __shfl_xor_sync(~0u, s1, 2);
            l0 = l0 * cr0 + s0; l1 = l1 * cr1 + s1;
            m0 = mn0; m1 = mn1;
            #pragma unroll
            for (int nt2 = 0; nt2 < 4; nt2++) {
                O[nt2][0] *= cr0; O[nt2][1] *= cr0;
                O[nt2][2] *= cr1; O[nt2][3] *= cr1;
            }

            // O += P V, 3-term bf16 (P from regs)
            #pragma unroll
            for (int kc = 0; kc < 4; kc++) {
                uint32_t ph[4], pl[4];
                split_pk(c[2*kc][0],   c[2*kc][1],   ph[0], pl[0]);
                split_pk(c[2*kc][2],   c[2*kc][3],   ph[1], pl[1]);
                split_pk(c[2*kc+1][0], c[2*kc+1][1], ph[2], pl[2]);
                split_pk(c[2*kc+1][2], c[2*kc+1][3], ph[3], pl[3]);
                int vcol = j0 / 2 + kc * 8 + tg;
                #pragma unroll
                for (int nt2 = 0; nt2 < 4; nt2++) {
                    int vb = (nt2 * 8 + g) * 196 + vcol;
                    uint32_t bh0 = Vts[vb], bh1 = Vts[vb + 4];
                    uint32_t bl0 = Vtl[vb], bl1 = Vtl[vb + 4];
                    mma_bf16(O[nt2], ph, bh0, bh1);
                    mma_bf16(O[nt2], pl, bh0, bh1);
                    mma_bf16(O[nt2], ph, bl0, bl1);
                }
            }
        }

        // finalize: normalize, gate, store
        float iv0 = 1.f / l0, iv1 = 1.f / l1;
        #pragma unroll
        for (int nt2 = 0; nt2 < 4; nt2++) {
            int d = nt2 * 8 + 2 * tg;
            int qa = q0 + g, qb = q0 + g + 8;
            float2 ga = *(const float2*)(g_G + base + (size_t)qa * DH + d);
            float2 gb = *(const float2*)(g_G + base + (size_t)qb * DH + d);
            *(float2*)(g_OG + (size_t)(i * NN + qa) * CIN + h * DH + d) =
                make_float2(O[nt2][0] * iv0 * ga.x, O[nt2][1] * iv0 * ga.y);
            *(float2*)(g_OG + (size_t)(i * NN + qb) * CIN + h * DH + d) =
                make_float2(O[nt2][2] * iv1 * gb.x, O[nt2][3] * iv1 * gb.y);
        }
    }
}

// ---------------- K4: output GEMM via tf32 mma ----------------
__global__ void __launch_bounds__(256, 1) out_mma_kernel(const float* __restrict__ bo,
                                                         float* __restrict__ out) {
    extern __shared__ float sm[];
    float* As = sm;
    float* Bs = sm + 128 * PAD_A;
    int tid = threadIdx.x;
    int m0  = blockIdx.x * 128;

    const float4* Ag = (const float4*)(g_OG + (size_t)m0 * CIN);
    const float4* Bg = (const float4*)g_Bout;
    #pragma unroll
    for (int r = 0; r < 16; r++) {
        int f = tid + r * 256;
        int row = f >> 5, c4 = f & 31;
        float4 av = Ag[f];
        av.x = tf32r(av.x); av.y = tf32r(av.y); av.z = tf32r(av.z); av.w = tf32r(av.w);
        *(float4*)(As + row * PAD_A + c4 * 4) = av;
        *(float4*)(Bs + row * PAD_B + c4 * 4) = Bg[f];
    }
    __syncthreads();

    int warp = tid >> 5, lane = tid & 31;
    int wm = (warp >> 1) * 32;
    int wn = (warp & 1) * 64;
    int g  = lane >> 2, tg = lane & 3;

    float c[2][8][4];
    #pragma unroll
    for (int a = 0; a < 2; a++)
        #pragma unroll
        for (int b = 0; b < 8; b++)
            #pragma unroll
            for (int e = 0; e < 4; e++) c[a][b][e] = 0.f;

    for (int k0 = 0; k0 < 128; k0 += 8) {
        uint32_t a[2][4];
        #pragma unroll
        for (int mt = 0; mt < 2; mt++) {
            const float* ap = As + (wm + mt * 16 + g) * PAD_A + k0 + tg;
            a[mt][0] = __float_as_uint(ap[0]);
            a[mt][1] = __float_as_uint(ap[8 * PAD_A]);
            a[mt][2] = __float_as_uint(ap[4]);
            a[mt][3] = __float_as_uint(ap[8 * PAD_A + 4]);
        }
        #pragma unroll
        for (int nt = 0; nt < 8; nt++) {
            const float* bp = Bs + (k0 + tg) * PAD_B + wn + nt * 8 + g;
            uint32_t b0 = __float_as_uint(bp[0]);
            uint32_t b1 = __float_as_uint(bp[4 * PAD_B]);
            #pragma unroll
            for (int mt = 0; mt < 2; mt++)
                mma_tf32(c[mt][nt], a[mt][0], a[mt][1], a[mt][2], a[mt][3], b0, b1);
        }
    }

    #pragma unroll
    for (int nt = 0; nt < 8; nt++) {
        int n = wn + nt * 8 + 2 * tg;
        float bo0 = bo[n], bo1 = bo[n + 1];
        #pragma unroll
        for (int mt = 0; mt < 2; mt++) {
            #pragma unroll
            for (int rr = 0; rr < 2; rr++) {
                int m = m0 + wm + mt * 16 + g + rr * 8;
                float* dst = out + (size_t)m * CIN + n;
                *(float2*)dst = make_float2(c[mt][nt][rr*2+0] + bo0,
                                            c[mt][nt][rr*2+1] + bo1);
            }
        }
    }
}

// ---------------- launch ----------------
extern "C" void kernel_launch(void* const* d_in, const int* in_sizes, int n_in,
                              void* d_out, int out_size) {
    const float* x     = (const float*)d_in[0];
    const float* mask  = (const float*)d_in[1];
    const float* gamma = (const float*)d_in[2];
    const float* beta  = (const float*)d_in[3];
    const float* wbias = (const float*)d_in[4];
    const float* wq    = (const float*)d_in[5];
    const float* wk    = (const float*)d_in[6];
    const float* wv    = (const float*)d_in[7];
    const float* wg    = (const float*)d_in[8];
    const float* bg    = (const float*)d_in[9];
    const float* wo    = (const float*)d_in[10];
    const float* bo    = (const float*)d_in[11];
    float* out = (float*)d_out;

    const int smem_gemm = 128 * PAD_A * 4 + 128 * PAD_B * 4;   // 137216
    const int smem_attn = (7680*2 + 6272*2 + 384) * 4;          // 113152
    cudaFuncSetAttribute(proj_mma_kernel, cudaFuncAttributeMaxDynamicSharedMemorySize, smem_gemm);
    cudaFuncSetAttribute(out_mma_kernel,  cudaFuncAttributeMaxDynamicSharedMemorySize, smem_gemm);
    cudaFuncSetAttribute(attn_bf16_kernel, cudaFuncAttributeMaxDynamicSharedMemorySize, smem_attn);

    pack_kernel<<<256, 256>>>(wq, wk, wv, wg, wo);
    ln_kernel<<<M_TOT / 8, 256>>>(x, gamma, beta, wbias);
    proj_mma_kernel<<<dim3(NH, M_TOT / 128), 256, smem_gemm>>>(bg);
    attn_bf16_kernel<<<dim3(NN, NH), 256, smem_attn>>>(mask);
    out_mma_kernel<<<M_TOT / 128, 256, smem_gemm>>>(bo, out);
}